// round 5
// baseline (speedup 1.0000x reference)
#include <cuda_runtime.h>
#include <math.h>

#define BATCH 8
#define NPTS  8192
#define MCL   512
#define NSAMP 64

// Output layout (float32, flattened tuple concat):
//   new_xyz  [B,M,3]   -> 12288
//   idx      [B,M,64]  -> 262144 (as float)
//   attention[B,M]     -> 4096
//   orientation[B,M]   -> 4096
#define OUT_XYZ 0
#define OUT_IDX (BATCH*MCL*3)
#define OUT_ATT (OUT_IDX + BATCH*MCL*NSAMP)
#define OUT_ORI (OUT_ATT + BATCH*MCL)

__device__ int g_idx[BATCH * MCL * NSAMP];

// ---------------- packed f32x2 helpers ----------------
__device__ __forceinline__ unsigned long long pack2dup(float a) {
    unsigned long long r;
    asm("mov.b64 %0, {%1, %1};" : "=l"(r) : "f"(a));
    return r;
}
__device__ __forceinline__ void unpack2(unsigned long long v, float& lo, float& hi) {
    asm("mov.b64 {%0, %1}, %2;" : "=f"(lo), "=f"(hi) : "l"(v));
}
__device__ __forceinline__ void fma2(unsigned long long& d, unsigned long long a, unsigned long long b) {
    asm("fma.rn.f32x2 %0, %1, %2, %0;" : "+l"(d) : "l"(a), "l"(b));
}

// =====================================================================
// Kernel 1: ball query + new_xyz copy + idx output
// Grid: BATCH*16 blocks, 256 threads. Each block: one batch, 32 centers.
// xyz[b] staged in SMEM (96KB). One warp per center, ballot-based
// "first 64 valid by index" collection with early exit.
// =====================================================================
__global__ void __launch_bounds__(256)
ball_query_kernel(const float* __restrict__ xyz, float* __restrict__ out)
{
    extern __shared__ float smem[];
    float* sxyz = smem;                          // NPTS*3 floats
    int*   sidx = (int*)(smem + NPTS * 3);       // 8 warps * NSAMP ints

    const int b     = blockIdx.x >> 4;
    const int chunk = blockIdx.x & 15;
    const float* xb = xyz + (size_t)b * NPTS * 3;

    const float4* xb4 = (const float4*)xb;       // NPTS*3 = 24576, /4 = 6144
    for (int i = threadIdx.x; i < NPTS * 3 / 4; i += 256)
        ((float4*)sxyz)[i] = xb4[i];
    __syncthreads();

    const int m0 = chunk * 32;
    // new_xyz = xyz[:, :512] for this block's 32 centers
    for (int i = threadIdx.x; i < 96; i += 256)
        out[OUT_XYZ + ((size_t)b * MCL + m0) * 3 + i] = sxyz[m0 * 3 + i];

    const int warp = threadIdx.x >> 5;
    const int lane = threadIdx.x & 31;
    int* wbuf = sidx + warp * NSAMP;

    for (int mi = warp; mi < 32; mi += 8) {
        const int m = m0 + mi;
        const float cx = sxyz[m * 3 + 0];
        const float cy = sxyz[m * 3 + 1];
        const float cz = sxyz[m * 3 + 2];
        int cnt = 0;
        for (int j = 0; j < NPTS; j += 32) {
            const int p = j + lane;
            // match XLA's unfused (dx*dx + dy*dy) + dz*dz at the boundary
            float dx = __fsub_rn(cx, sxyz[p * 3 + 0]);
            float dy = __fsub_rn(cy, sxyz[p * 3 + 1]);
            float dz = __fsub_rn(cz, sxyz[p * 3 + 2]);
            float d2 = __fadd_rn(__fadd_rn(__fmul_rn(dx, dx), __fmul_rn(dy, dy)),
                                 __fmul_rn(dz, dz));
            bool valid = d2 < 4.0f;
            unsigned msk = __ballot_sync(0xffffffffu, valid);
            int pos = cnt + __popc(msk & ((1u << lane) - 1u));
            if (valid && pos < NSAMP) wbuf[pos] = p;
            cnt += __popc(msk);
            if (cnt >= NSAMP) break;               // uniform across warp
        }
        __syncwarp();
        const int first = wbuf[0];                 // >=1 valid (center itself)
        const int c = cnt < NSAMP ? cnt : NSAMP;
        const long base = ((long)b * MCL + m) * NSAMP;
        for (int k = lane; k < NSAMP; k += 32) {
            const int v = (k < c) ? wbuf[k] : first;
            g_idx[base + k] = v;
            out[OUT_IDX + base + k] = (float)v;
        }
        __syncwarp();
    }
}

// =====================================================================
// Kernel 2: per-(b,m) fused MLP. Grid: 4096 blocks, 256 threads.
// Packed f32x2 FMA throughout the big layers. h3 never materialized:
// running max in registers (relu∘max == max∘relu).
// =====================================================================
__global__ void __launch_bounds__(256, 2)
mlp_kernel(const float* __restrict__ xyz,
           const float* __restrict__ W1, const float* __restrict__ b1,
           const float* __restrict__ W2, const float* __restrict__ b2,
           const float* __restrict__ W3, const float* __restrict__ b3,
           const float* __restrict__ W4, const float* __restrict__ b4,
           const float* __restrict__ W5, const float* __restrict__ b5,
           const float* __restrict__ Wa, const float* __restrict__ ba,
           const float* __restrict__ Wo, const float* __restrict__ bo,
           float* __restrict__ out)
{
    extern __shared__ float sm[];
    float* s_g    = sm;             // 192
    float* s_h1   = sm + 192;       // 64*64  = 4096
    float* s_h2   = s_h1 + 4096;    // 64*128 = 8192
    float* s_red  = s_h2 + 8192;    // 8*256  = 2048
    float* s_hmax = s_red + 2048;   // 256
    float* s_h4   = s_hmax + 256;   // 128
    float* s_h5   = s_h4 + 128;     // 64

    const int bm = blockIdx.x;
    const int b  = bm >> 9;
    const int m  = bm & (MCL - 1);
    const float* xb = xyz + (size_t)b * NPTS * 3;
    const int tid  = threadIdx.x;
    const int warp = tid >> 5;
    const int lane = tid & 31;
    const int s0   = warp * 8;

    // ---- gather g = (xyz[idx] - center) * 0.5 ----
    if (tid < NSAMP) {
        const int p = g_idx[(size_t)bm * NSAMP + tid];
        const float cx = xb[m * 3 + 0], cy = xb[m * 3 + 1], cz = xb[m * 3 + 2];
        s_g[tid * 3 + 0] = (xb[p * 3 + 0] - cx) * 0.5f;
        s_g[tid * 3 + 1] = (xb[p * 3 + 1] - cy) * 0.5f;
        s_g[tid * 3 + 2] = (xb[p * 3 + 2] - cz) * 0.5f;
    }
    __syncthreads();

    // ---- h1 = relu(g @ W1 + b1)  [64,64] ----
    for (int o = tid; o < NSAMP * 64; o += 256) {
        const int s = o >> 6, c = o & 63;
        float v = b1[c];
        v = fmaf(s_g[s * 3 + 0], W1[c], v);
        v = fmaf(s_g[s * 3 + 1], W1[64 + c], v);
        v = fmaf(s_g[s * 3 + 2], W1[128 + c], v);
        s_h1[o] = fmaxf(v, 0.0f);
    }
    __syncthreads();

    // ---- h2 = relu(h1 @ W2 + b2)  [64,128], warp-local stripe ----
    {
        unsigned long long acc[8][2];
        const unsigned long long* b2p = (const unsigned long long*)b2;
        #pragma unroll
        for (int i = 0; i < 8; i++) {
            acc[i][0] = b2p[lane];
            acc[i][1] = b2p[lane + 32];
        }
        const unsigned long long* W2p = (const unsigned long long*)W2;
        #pragma unroll 4
        for (int k = 0; k < 64; k += 2) {
            unsigned long long w00 = W2p[(size_t)k * 64 + lane];
            unsigned long long w01 = W2p[(size_t)k * 64 + lane + 32];
            unsigned long long w10 = W2p[(size_t)(k + 1) * 64 + lane];
            unsigned long long w11 = W2p[(size_t)(k + 1) * 64 + lane + 32];
            #pragma unroll
            for (int i = 0; i < 8; i++) {
                unsigned long long a0 = pack2dup(s_h1[(s0 + i) * 64 + k]);
                unsigned long long a1 = pack2dup(s_h1[(s0 + i) * 64 + k + 1]);
                fma2(acc[i][0], a0, w00); fma2(acc[i][1], a0, w01);
                fma2(acc[i][0], a1, w10); fma2(acc[i][1], a1, w11);
            }
        }
        #pragma unroll
        for (int i = 0; i < 8; i++) {
            float lo, hi;
            unpack2(acc[i][0], lo, hi);
            ((float2*)(s_h2 + (s0 + i) * 128))[lane]      = make_float2(fmaxf(lo, 0.f), fmaxf(hi, 0.f));
            unpack2(acc[i][1], lo, hi);
            ((float2*)(s_h2 + (s0 + i) * 128))[lane + 32] = make_float2(fmaxf(lo, 0.f), fmaxf(hi, 0.f));
        }
    }
    __syncwarp();   // h2 stripe is warp-local: produced and consumed by this warp

    // ---- h3 = h2 @ W3 + b3, fused max over s (never materialized) ----
    {
        unsigned long long acc[8][4];
        const unsigned long long* b3p = (const unsigned long long*)b3;
        #pragma unroll
        for (int i = 0; i < 8; i++)
            #pragma unroll
            for (int j = 0; j < 4; j++) acc[i][j] = b3p[lane + 32 * j];

        const unsigned long long* W3p = (const unsigned long long*)W3;
        for (int kb = 0; kb < 128; kb += 32) {
            __syncthreads();   // keep 8 warps convergent -> W3 rereads hit L1
            #pragma unroll 2
            for (int k = kb; k < kb + 32; k += 2) {
                unsigned long long w0[4], w1[4];
                #pragma unroll
                for (int j = 0; j < 4; j++) {
                    w0[j] = W3p[(size_t)k * 128 + lane + 32 * j];
                    w1[j] = W3p[(size_t)(k + 1) * 128 + lane + 32 * j];
                }
                #pragma unroll
                for (int i = 0; i < 8; i++) {
                    unsigned long long a0 = pack2dup(s_h2[(s0 + i) * 128 + k]);
                    unsigned long long a1 = pack2dup(s_h2[(s0 + i) * 128 + k + 1]);
                    #pragma unroll
                    for (int j = 0; j < 4; j++) {
                        fma2(acc[i][j], a0, w0[j]);
                        fma2(acc[i][j], a1, w1[j]);
                    }
                }
            }
        }
        // per-warp max over its 8 samples
        #pragma unroll
        for (int j = 0; j < 4; j++) {
            float mlo = -3.402823466e38f, mhi = -3.402823466e38f;
            #pragma unroll
            for (int i = 0; i < 8; i++) {
                float lo, hi;
                unpack2(acc[i][j], lo, hi);
                mlo = fmaxf(mlo, lo);
                mhi = fmaxf(mhi, hi);
            }
            ((float2*)(s_red + warp * 256))[lane + 32 * j] = make_float2(mlo, mhi);
        }
    }
    __syncthreads();

    // ---- cross-warp max + relu -> hmax[256] ----
    {
        float v = s_red[tid];
        #pragma unroll
        for (int w = 1; w < 8; w++) v = fmaxf(v, s_red[w * 256 + tid]);
        s_hmax[tid] = fmaxf(v, 0.0f);
    }
    __syncthreads();

    // ---- h4 = hmax @ W4 + b4  [128] ----
    if (tid < 128) {
        float acc = b4[tid];
        #pragma unroll 4
        for (int e = 0; e < 256; e++)
            acc = fmaf(s_hmax[e], W4[(size_t)e * 128 + tid], acc);
        s_h4[tid] = acc;
    }
    __syncthreads();

    // ---- h5 = h4 @ W5 + b5  [64] ----
    if (tid < 64) {
        float acc = b5[tid];
        #pragma unroll 4
        for (int d = 0; d < 128; d++)
            acc = fmaf(s_h4[d], W5[(size_t)d * 64 + tid], acc);
        s_h5[tid] = acc;
    }
    __syncthreads();

    // ---- heads: attention (softplus) + orientation (atan2) ----
    if (warp == 0) {
        const float h5a = s_h5[lane], h5b = s_h5[lane + 32];
        float pa = h5a * Wa[lane]            + h5b * Wa[lane + 32];
        float p0 = h5a * Wo[lane * 2 + 0]    + h5b * Wo[(lane + 32) * 2 + 0];
        float p1 = h5a * Wo[lane * 2 + 1]    + h5b * Wo[(lane + 32) * 2 + 1];
        #pragma unroll
        for (int off = 16; off; off >>= 1) {
            pa += __shfl_xor_sync(0xffffffffu, pa, off);
            p0 += __shfl_xor_sync(0xffffffffu, p0, off);
            p1 += __shfl_xor_sync(0xffffffffu, p1, off);
        }
        if (lane == 0) {
            const float x  = pa + ba[0];
            const float att = fmaxf(x, 0.0f) + log1pf(expf(-fabsf(x)));  // jax softplus
            float o0 = p0 + bo[0];
            float o1 = p1 + bo[1];
            const float inv = 1.0f / sqrtf(fmaxf(o0 * o0 + o1 * o1, 1e-8f));
            o0 *= inv; o1 *= inv;
            out[OUT_ATT + bm] = att;
            out[OUT_ORI + bm] = atan2f(o1, o0);
        }
    }
}

// =====================================================================
extern "C" void kernel_launch(void* const* d_in, const int* in_sizes, int n_in,
                              void* d_out, int out_size)
{
    const float* xyz = (const float*)d_in[0];
    const float* W1  = (const float*)d_in[1];
    const float* b1  = (const float*)d_in[2];
    const float* W2  = (const float*)d_in[3];
    const float* b2  = (const float*)d_in[4];
    const float* W3  = (const float*)d_in[5];
    const float* b3  = (const float*)d_in[6];
    const float* W4  = (const float*)d_in[7];
    const float* b4  = (const float*)d_in[8];
    const float* W5  = (const float*)d_in[9];
    const float* b5  = (const float*)d_in[10];
    const float* Wa  = (const float*)d_in[11];
    const float* ba  = (const float*)d_in[12];
    const float* Wo  = (const float*)d_in[13];
    const float* bo  = (const float*)d_in[14];
    float* out = (float*)d_out;

    const int smem1 = NPTS * 3 * 4 + 8 * NSAMP * 4;           // 100352 B
    const int smem2 = (192 + 4096 + 8192 + 2048 + 256 + 128 + 64) * 4;  // 59904 B

    cudaFuncSetAttribute(ball_query_kernel,
                         cudaFuncAttributeMaxDynamicSharedMemorySize, smem1);
    cudaFuncSetAttribute(mlp_kernel,
                         cudaFuncAttributeMaxDynamicSharedMemorySize, smem2);

    ball_query_kernel<<<BATCH * 16, 256, smem1>>>(xyz, out);
    mlp_kernel<<<BATCH * MCL, 256, smem2>>>(xyz, W1, b1, W2, b2, W3, b3,
                                            W4, b4, W5, b5, Wa, ba, Wo, bo, out);
}

// round 6
// speedup vs baseline: 1.2341x; 1.2341x over previous
#include <cuda_runtime.h>
#include <math.h>
#include <stdint.h>

#define BATCH 8
#define NPTS  8192
#define MCL   512
#define NSAMP 64

// Output layout (float32, flattened tuple concat):
//   new_xyz  [B,M,3], idx [B,M,64] (as float), attention [B,M], orientation [B,M]
#define OUT_XYZ 0
#define OUT_IDX (BATCH*MCL*3)
#define OUT_ATT (OUT_IDX + BATCH*MCL*NSAMP)
#define OUT_ORI (OUT_ATT + BATCH*MCL)

__device__ int g_idx[BATCH * MCL * NSAMP];

// ---------------- packed f32x2 helpers ----------------
__device__ __forceinline__ unsigned long long pack2dup(float a) {
    unsigned long long r;
    asm("mov.b64 %0, {%1, %1};" : "=l"(r) : "f"(a));
    return r;
}
__device__ __forceinline__ void unpack2(unsigned long long v, float& lo, float& hi) {
    asm("mov.b64 {%0, %1}, %2;" : "=f"(lo), "=f"(hi) : "l"(v));
}
__device__ __forceinline__ void fma2(unsigned long long& d, unsigned long long a, unsigned long long b) {
    asm("fma.rn.f32x2 %0, %1, %2, %0;" : "+l"(d) : "l"(a), "l"(b));
}
// ---------------- cp.async helpers ----------------
__device__ __forceinline__ void cp_async16(void* dst, const void* src) {
    unsigned d = (unsigned)__cvta_generic_to_shared(dst);
    asm volatile("cp.async.ca.shared.global [%0], [%1], 16;" :: "r"(d), "l"(src));
}
#define CP_COMMIT() asm volatile("cp.async.commit_group;")
#define CP_WAIT(n)  asm volatile("cp.async.wait_group %0;" :: "n"(n))

// =====================================================================
// Kernel 1: ball query + new_xyz copy + idx output  (unchanged, passed)
// =====================================================================
__global__ void __launch_bounds__(256)
ball_query_kernel(const float* __restrict__ xyz, float* __restrict__ out)
{
    extern __shared__ float smem[];
    float* sxyz = smem;                          // NPTS*3 floats
    int*   sidx = (int*)(smem + NPTS * 3);       // 8 warps * NSAMP ints

    const int b     = blockIdx.x >> 4;
    const int chunk = blockIdx.x & 15;
    const float* xb = xyz + (size_t)b * NPTS * 3;

    const float4* xb4 = (const float4*)xb;
    for (int i = threadIdx.x; i < NPTS * 3 / 4; i += 256)
        ((float4*)sxyz)[i] = xb4[i];
    __syncthreads();

    const int m0 = chunk * 32;
    for (int i = threadIdx.x; i < 96; i += 256)
        out[OUT_XYZ + ((size_t)b * MCL + m0) * 3 + i] = sxyz[m0 * 3 + i];

    const int warp = threadIdx.x >> 5;
    const int lane = threadIdx.x & 31;
    int* wbuf = sidx + warp * NSAMP;

    for (int mi = warp; mi < 32; mi += 8) {
        const int m = m0 + mi;
        const float cx = sxyz[m * 3 + 0];
        const float cy = sxyz[m * 3 + 1];
        const float cz = sxyz[m * 3 + 2];
        int cnt = 0;
        for (int j = 0; j < NPTS; j += 32) {
            const int p = j + lane;
            float dx = __fsub_rn(cx, sxyz[p * 3 + 0]);
            float dy = __fsub_rn(cy, sxyz[p * 3 + 1]);
            float dz = __fsub_rn(cz, sxyz[p * 3 + 2]);
            float d2 = __fadd_rn(__fadd_rn(__fmul_rn(dx, dx), __fmul_rn(dy, dy)),
                                 __fmul_rn(dz, dz));
            bool valid = d2 < 4.0f;
            unsigned msk = __ballot_sync(0xffffffffu, valid);
            int pos = cnt + __popc(msk & ((1u << lane) - 1u));
            if (valid && pos < NSAMP) wbuf[pos] = p;
            cnt += __popc(msk);
            if (cnt >= NSAMP) break;
        }
        __syncwarp();
        const int first = wbuf[0];
        const int c = cnt < NSAMP ? cnt : NSAMP;
        const long base = ((long)b * MCL + m) * NSAMP;
        for (int k = lane; k < NSAMP; k += 32) {
            const int v = (k < c) ? wbuf[k] : first;
            g_idx[base + k] = v;
            out[OUT_IDX + base + k] = (float)v;
        }
        __syncwarp();
    }
}

// =====================================================================
// Kernel 2: fused MLP, v2.
//  - 3 CTAs/SM (regs<=85), 68KB smem
//  - W2/W3 staged in SMEM via cp.async double buffering
//  - h3 split into two N-half passes (acc[8][2]) so registers fit;
//    W3 cols for each half streamed separately (total traffic unchanged)
// SMEM map (floats):
//   [0)      s_h2   8192
//   [8192)   s_red  2048
//   [10240)  s_hmax 256
//   [10496)  s_h4   128
//   [10624)  s_h5   64
//   [10688)  union U (8192):
//       phase A: s_g 192 | s_h1 4096 | s_w2 2x1024
//       phase B: s_w3 2x4096
// total 18880 floats = 75520 B
// =====================================================================
__global__ void __launch_bounds__(256, 3)
mlp_kernel(const float* __restrict__ xyz,
           const float* __restrict__ W1, const float* __restrict__ b1,
           const float* __restrict__ W2, const float* __restrict__ b2,
           const float* __restrict__ W3, const float* __restrict__ b3,
           const float* __restrict__ W4, const float* __restrict__ b4,
           const float* __restrict__ W5, const float* __restrict__ b5,
           const float* __restrict__ Wa, const float* __restrict__ ba,
           const float* __restrict__ Wo, const float* __restrict__ bo,
           float* __restrict__ out)
{
    extern __shared__ float sm[];
    float* s_h2   = sm;                // 8192
    float* s_red  = sm + 8192;         // 2048
    float* s_hmax = sm + 10240;        // 256
    float* s_h4   = sm + 10496;        // 128
    float* s_h5   = sm + 10624;        // 64
    float* s_u    = sm + 10688;        // 8192 union
    float* s_g    = s_u;               // 192
    float* s_h1   = s_u + 192;         // 4096
    float* s_w2   = s_u + 4288;        // 2*1024
    float* s_w3   = s_u;               // 2*4096 (phase B)

    const int bm = blockIdx.x;
    const int b  = bm >> 9;
    const int m  = bm & (MCL - 1);
    const float* xb = xyz + (size_t)b * NPTS * 3;
    const int tid  = threadIdx.x;
    const int warp = tid >> 5;
    const int lane = tid & 31;
    const int s0   = warp * 8;

    // prefetch W2 chunk 0 (8 rows x 128 = 1024 floats), group 0
    cp_async16(s_w2 + tid * 4, W2 + tid * 4);
    CP_COMMIT();

    // ---- gather g = (xyz[idx] - center) * 0.5 ----
    if (tid < NSAMP) {
        const int p = g_idx[(size_t)bm * NSAMP + tid];
        const float cx = xb[m * 3 + 0], cy = xb[m * 3 + 1], cz = xb[m * 3 + 2];
        s_g[tid * 3 + 0] = (xb[p * 3 + 0] - cx) * 0.5f;
        s_g[tid * 3 + 1] = (xb[p * 3 + 1] - cy) * 0.5f;
        s_g[tid * 3 + 2] = (xb[p * 3 + 2] - cz) * 0.5f;
    }
    __syncthreads();

    // ---- h1 = relu(g @ W1 + b1)  [64,64] ----
    for (int o = tid; o < NSAMP * 64; o += 256) {
        const int s = o >> 6, c = o & 63;
        float v = b1[c];
        v = fmaf(s_g[s * 3 + 0], W1[c], v);
        v = fmaf(s_g[s * 3 + 1], W1[64 + c], v);
        v = fmaf(s_g[s * 3 + 2], W1[128 + c], v);
        s_h1[o] = fmaxf(v, 0.0f);
    }
    // no explicit sync needed: the pipeline __syncthreads below publishes s_h1

    // ---- h2 = relu(h1 @ W2 + b2)  [64,128], W2 streamed in 8 chunks of 8 rows
    unsigned long long acc2[8][2];
    {
        const unsigned long long* b2p = (const unsigned long long*)b2;
        const unsigned long long bv0 = b2p[lane], bv1 = b2p[lane + 32];
        #pragma unroll
        for (int i = 0; i < 8; i++) { acc2[i][0] = bv0; acc2[i][1] = bv1; }

        for (int c = 0; c < 8; c++) {
            if (c + 1 < 8) {
                cp_async16(s_w2 + ((c + 1) & 1) * 1024 + tid * 4,
                           W2 + (c + 1) * 1024 + tid * 4);
                CP_COMMIT();
                CP_WAIT(1);
            } else {
                CP_WAIT(0);
            }
            __syncthreads();
            const unsigned long long* wb =
                (const unsigned long long*)(s_w2 + (c & 1) * 1024);
            const int kb = c * 8;
            #pragma unroll
            for (int r = 0; r < 8; r += 2) {
                unsigned long long w00 = wb[r * 64 + lane];
                unsigned long long w01 = wb[r * 64 + lane + 32];
                unsigned long long w10 = wb[(r + 1) * 64 + lane];
                unsigned long long w11 = wb[(r + 1) * 64 + lane + 32];
                #pragma unroll
                for (int i = 0; i < 8; i++) {
                    float2 av = *(const float2*)(s_h1 + (s0 + i) * 64 + kb + r);
                    unsigned long long a0 = pack2dup(av.x);
                    unsigned long long a1 = pack2dup(av.y);
                    fma2(acc2[i][0], a0, w00); fma2(acc2[i][1], a0, w01);
                    fma2(acc2[i][0], a1, w10); fma2(acc2[i][1], a1, w11);
                }
            }
            __syncthreads();
        }
    }

    // phase A memory now dead for all threads (last sync above) ->
    // issue W3 chunk 0 (half 0, rows 0..31, cols 0..127): 4096 floats
    {
        #pragma unroll
        for (int t = 0; t < 4; t++) {
            int idx = tid + t * 256;                 // float4 index
            int r = idx >> 5, c4 = idx & 31;
            cp_async16(s_w3 + idx * 4, W3 + r * 256 + c4 * 4);
        }
        CP_COMMIT();
    }

    // h2 writeout (relu) — warp-local stripe of s_h2
    #pragma unroll
    for (int i = 0; i < 8; i++) {
        float lo, hi;
        unpack2(acc2[i][0], lo, hi);
        ((float2*)(s_h2 + (s0 + i) * 128))[lane]      = make_float2(fmaxf(lo, 0.f), fmaxf(hi, 0.f));
        unpack2(acc2[i][1], lo, hi);
        ((float2*)(s_h2 + (s0 + i) * 128))[lane + 32] = make_float2(fmaxf(lo, 0.f), fmaxf(hi, 0.f));
    }

    // ---- h3 = max_s(h2 @ W3 + b3): two N-half passes, W3 streamed ----
    {
        const unsigned long long* b3p = (const unsigned long long*)b3;
        unsigned long long acc[8][2];
        for (int cc = 0; cc < 8; cc++) {
            const int nh = cc >> 2;            // N-half of this chunk
            const int kb = (cc & 3) * 32;      // k base
            if (cc + 1 < 8) {
                const int nh2 = (cc + 1) >> 2, kb2 = ((cc + 1) & 3) * 32;
                float* dst = s_w3 + ((cc + 1) & 1) * 4096;
                #pragma unroll
                for (int t = 0; t < 4; t++) {
                    int idx = tid + t * 256;
                    int r = idx >> 5, c4 = idx & 31;
                    cp_async16(dst + idx * 4,
                               W3 + (size_t)(kb2 + r) * 256 + nh2 * 128 + c4 * 4);
                }
                CP_COMMIT();
                CP_WAIT(1);
            } else {
                CP_WAIT(0);
            }
            __syncthreads();

            if ((cc & 3) == 0) {
                const unsigned long long bv0 = b3p[nh * 64 + lane];
                const unsigned long long bv1 = b3p[nh * 64 + lane + 32];
                #pragma unroll
                for (int i = 0; i < 8; i++) { acc[i][0] = bv0; acc[i][1] = bv1; }
            }

            const unsigned long long* wb =
                (const unsigned long long*)(s_w3 + (cc & 1) * 4096);
            #pragma unroll 2
            for (int r = 0; r < 32; r += 2) {
                unsigned long long w00 = wb[r * 64 + lane];
                unsigned long long w01 = wb[r * 64 + lane + 32];
                unsigned long long w10 = wb[(r + 1) * 64 + lane];
                unsigned long long w11 = wb[(r + 1) * 64 + lane + 32];
                const int k = kb + r;
                #pragma unroll
                for (int i = 0; i < 8; i++) {
                    float2 av = *(const float2*)(s_h2 + (s0 + i) * 128 + k);
                    unsigned long long a0 = pack2dup(av.x);
                    unsigned long long a1 = pack2dup(av.y);
                    fma2(acc[i][0], a0, w00); fma2(acc[i][1], a0, w01);
                    fma2(acc[i][0], a1, w10); fma2(acc[i][1], a1, w11);
                }
            }

            if ((cc & 3) == 3) {   // per-warp max over its 8 samples, this half
                float2* rd = (float2*)(s_red + warp * 256);
                #pragma unroll
                for (int j = 0; j < 2; j++) {
                    float mlo = -3.402823466e38f, mhi = -3.402823466e38f;
                    #pragma unroll
                    for (int i = 0; i < 8; i++) {
                        float lo, hi;
                        unpack2(acc[i][j], lo, hi);
                        mlo = fmaxf(mlo, lo);
                        mhi = fmaxf(mhi, hi);
                    }
                    rd[nh * 64 + lane + 32 * j] = make_float2(mlo, mhi);
                }
            }
            __syncthreads();
        }
    }

    // ---- cross-warp max + relu -> hmax[256] ----
    {
        float v = s_red[tid];
        #pragma unroll
        for (int w = 1; w < 8; w++) v = fmaxf(v, s_red[w * 256 + tid]);
        s_hmax[tid] = fmaxf(v, 0.0f);
    }
    __syncthreads();

    // ---- h4 = hmax @ W4 + b4  [128] ----
    if (tid < 128) {
        float acc = b4[tid];
        #pragma unroll 8
        for (int e = 0; e < 256; e++)
            acc = fmaf(s_hmax[e], W4[(size_t)e * 128 + tid], acc);
        s_h4[tid] = acc;
    }
    __syncthreads();

    // ---- h5 = h4 @ W5 + b5  [64] ----
    if (tid < 64) {
        float acc = b5[tid];
        #pragma unroll 8
        for (int d = 0; d < 128; d++)
            acc = fmaf(s_h4[d], W5[(size_t)d * 64 + tid], acc);
        s_h5[tid] = acc;
    }
    __syncthreads();

    // ---- heads: attention (softplus) + orientation (atan2) ----
    if (warp == 0) {
        const float h5a = s_h5[lane], h5b = s_h5[lane + 32];
        float pa = h5a * Wa[lane]         + h5b * Wa[lane + 32];
        float p0 = h5a * Wo[lane * 2 + 0] + h5b * Wo[(lane + 32) * 2 + 0];
        float p1 = h5a * Wo[lane * 2 + 1] + h5b * Wo[(lane + 32) * 2 + 1];
        #pragma unroll
        for (int off = 16; off; off >>= 1) {
            pa += __shfl_xor_sync(0xffffffffu, pa, off);
            p0 += __shfl_xor_sync(0xffffffffu, p0, off);
            p1 += __shfl_xor_sync(0xffffffffu, p1, off);
        }
        if (lane == 0) {
            const float x  = pa + ba[0];
            const float att = fmaxf(x, 0.0f) + log1pf(expf(-fabsf(x)));
            float o0 = p0 + bo[0];
            float o1 = p1 + bo[1];
            const float inv = 1.0f / sqrtf(fmaxf(o0 * o0 + o1 * o1, 1e-8f));
            o0 *= inv; o1 *= inv;
            out[OUT_ATT + bm] = att;
            out[OUT_ORI + bm] = atan2f(o1, o0);
        }
    }
}

// =====================================================================
extern "C" void kernel_launch(void* const* d_in, const int* in_sizes, int n_in,
                              void* d_out, int out_size)
{
    const float* xyz = (const float*)d_in[0];
    const float* W1  = (const float*)d_in[1];
    const float* b1  = (const float*)d_in[2];
    const float* W2  = (const float*)d_in[3];
    const float* b2  = (const float*)d_in[4];
    const float* W3  = (const float*)d_in[5];
    const float* b3  = (const float*)d_in[6];
    const float* W4  = (const float*)d_in[7];
    const float* b4  = (const float*)d_in[8];
    const float* W5  = (const float*)d_in[9];
    const float* b5  = (const float*)d_in[10];
    const float* Wa  = (const float*)d_in[11];
    const float* ba  = (const float*)d_in[12];
    const float* Wo  = (const float*)d_in[13];
    const float* bo  = (const float*)d_in[14];
    float* out = (float*)d_out;

    const int smem1 = NPTS * 3 * 4 + 8 * NSAMP * 4;   // 100352 B
    const int smem2 = 18880 * 4;                      // 75520 B

    cudaFuncSetAttribute(ball_query_kernel,
                         cudaFuncAttributeMaxDynamicSharedMemorySize, smem1);
    cudaFuncSetAttribute(mlp_kernel,
                         cudaFuncAttributeMaxDynamicSharedMemorySize, smem2);

    ball_query_kernel<<<BATCH * 16, 256, smem1>>>(xyz, out);
    mlp_kernel<<<BATCH * MCL, 256, smem2>>>(xyz, W1, b1, W2, b2, W3, b3,
                                            W4, b4, W5, b5, Wa, ba, Wo, bo, out);
}